// round 1
// baseline (speedup 1.0000x reference)
#include <cuda_runtime.h>
#include <cuda_bf16.h>

// NuclearLossFunc: loss = sum(x^2) / (B*C), x: (32,64,256,256) fp32
// = 134,217,728 elements. Pure HBM-bound reduction.
//
// Pass 1: grid-stride float4 squared-sum, per-block partial -> global scratch
// Pass 2: single block reduces partials in double, writes float result.
// Fully deterministic (fixed reduction tree, no float atomics).

#define NBLOCKS 1184           // 148 SMs * 8
#define NTHREADS 512

__device__ float g_partials[NBLOCKS];

__global__ __launch_bounds__(NTHREADS) void sqsum_kernel(
    const float4* __restrict__ in, long long n4)
{
    float s0 = 0.f, s1 = 0.f, s2 = 0.f, s3 = 0.f;
    long long idx    = (long long)blockIdx.x * blockDim.x + threadIdx.x;
    long long stride = (long long)gridDim.x * blockDim.x;

    for (long long i = idx; i < n4; i += stride) {
        float4 v = in[i];
        s0 = fmaf(v.x, v.x, s0);
        s1 = fmaf(v.y, v.y, s1);
        s2 = fmaf(v.z, v.z, s2);
        s3 = fmaf(v.w, v.w, s3);
    }
    float s = (s0 + s1) + (s2 + s3);

    // warp reduce
    #pragma unroll
    for (int o = 16; o > 0; o >>= 1)
        s += __shfl_xor_sync(0xffffffffu, s, o);

    __shared__ float ws[NTHREADS / 32];
    int lane = threadIdx.x & 31;
    int wid  = threadIdx.x >> 5;
    if (lane == 0) ws[wid] = s;
    __syncthreads();

    if (wid == 0) {
        s = (lane < NTHREADS / 32) ? ws[lane] : 0.f;
        #pragma unroll
        for (int o = 16; o > 0; o >>= 1)
            s += __shfl_xor_sync(0xffffffffu, s, o);
        if (lane == 0) g_partials[blockIdx.x] = s;
    }
}

__global__ __launch_bounds__(1024) void finalize_kernel(
    float* __restrict__ out, int nblocks, float scale)
{
    double s = 0.0;
    for (int i = threadIdx.x; i < nblocks; i += blockDim.x)
        s += (double)g_partials[i];

    // warp reduce in double
    #pragma unroll
    for (int o = 16; o > 0; o >>= 1)
        s += __shfl_xor_sync(0xffffffffu, s, o);

    __shared__ double ws[32];
    int lane = threadIdx.x & 31;
    int wid  = threadIdx.x >> 5;
    if (lane == 0) ws[wid] = s;
    __syncthreads();

    if (wid == 0) {
        s = (lane < 32) ? ws[lane] : 0.0;
        #pragma unroll
        for (int o = 16; o > 0; o >>= 1)
            s += __shfl_xor_sync(0xffffffffu, s, o);
        if (lane == 0) out[0] = (float)(s * (double)scale);
    }
}

extern "C" void kernel_launch(void* const* d_in, const int* in_sizes, int n_in,
                              void* d_out, int out_size)
{
    const float* x = (const float*)d_in[0];
    long long n = (long long)in_sizes[0];     // 134217728, divisible by 4
    long long n4 = n >> 2;

    // B*C = 32*64 = 2048; n = B*C*256*256 so B*C = n / 65536
    float scale = 1.0f / (float)(n / (256LL * 256LL));

    sqsum_kernel<<<NBLOCKS, NTHREADS>>>((const float4*)x, n4);
    finalize_kernel<<<1, 1024>>>((float*)d_out, NBLOCKS, scale);
}